// round 2
// baseline (speedup 1.0000x reference)
#include <cuda_runtime.h>
#include <cuda_bf16.h>
#include <stdint.h>

#define NN 8192
#define DD 128
#define KK 4096         // K = N/2
#define NKEEP (NN - KK) // 4096

// ---------------- device scratch (no allocations allowed) ----------------
__device__ float  g_norm[NN];     // f32 row L2 norm
__device__ float  g_dinvf[NN];    // f32 deg^-0.5 (0 if deg==0)
__device__ int    g_deg[NN];
__device__ double g_edot[NN];     // per sorted-edge-slot contribution (0 for dups)
__device__ float  g_wf[NN];       // final f32 weights
__device__ int    g_ei[NN];       // decoded edge sources
__device__ int    g_ej[NN];       // decoded edge targets
__device__ unsigned int       g_packed[NN];  // packed edges (i<<13|j), sorted
__device__ unsigned long long g_keys[NN];    // top-k sort keys
__device__ int    g_perm[KK];
__device__ int    g_sel[NN];
__device__ int    g_newmask[NN];
__device__ int    g_is64;

// ---------------- kernels ----------------

__global__ void zero_kernel() {
    int i = blockIdx.x * blockDim.x + threadIdx.x;
    if (i < NN) {
        g_edot[i] = 0.0;
        g_wf[i] = 0.0f;
        g_deg[i] = 0;
        g_sel[i] = 0;
        g_newmask[i] = 0;
    }
}

// Detect whether the edge buffer is int64 (odd 32-bit words all zero) or int32.
__global__ void detect_kernel(const unsigned int* __restrict__ e32) {
    int is64 = 1;
    #pragma unroll 1
    for (int k = 0; k < 64; k++) {
        if (e32[2 * k + 1] != 0u) { is64 = 0; break; }
    }
    g_is64 = is64;
}

// one warp per row: f32 norm via double sumsq
__global__ void norms_kernel(const float* __restrict__ x) {
    int warp = (blockIdx.x * blockDim.x + threadIdx.x) >> 5;
    int lane = threadIdx.x & 31;
    if (warp >= NN) return;
    const float4* row = (const float4*)(x + (size_t)warp * DD);
    float4 v = row[lane];
    double s = (double)v.x * v.x + (double)v.y * v.y + (double)v.z * v.z + (double)v.w * v.w;
    #pragma unroll
    for (int o = 16; o > 0; o >>= 1) s += __shfl_down_sync(0xffffffffu, s, o);
    if (lane == 0) g_norm[warp] = (float)sqrt(s);
}

// decode edges (int32 or int64) into g_ei/g_ej and packed keys
__global__ void pack_kernel(const void* __restrict__ edges) {
    int e = blockIdx.x * blockDim.x + threadIdx.x;
    if (e >= NN) return;
    int i, j;
    if (g_is64) {
        const long long* p = (const long long*)edges;
        i = (int)p[e];
        j = (int)p[NN + e];
    } else {
        const int* p = (const int*)edges;
        i = p[e];
        j = p[NN + e];
    }
    g_ei[e] = i;
    g_ej[e] = j;
    g_packed[e] = ((unsigned int)i << 13) | (unsigned int)j;
}

// bitonic sort of 8192 uint32 in one block (32KB static smem)
__global__ void sort32_kernel() {
    __shared__ unsigned int s[NN];
    int tid = threadIdx.x;
    for (int i = tid; i < NN; i += blockDim.x) s[i] = g_packed[i];
    __syncthreads();
    for (int k = 2; k <= NN; k <<= 1) {
        for (int j = k >> 1; j > 0; j >>= 1) {
            for (int i = tid; i < NN; i += blockDim.x) {
                int l = i ^ j;
                if (l > i) {
                    unsigned int a = s[i], b = s[l];
                    bool asc = ((i & k) == 0);
                    if ((a > b) == asc) { s[i] = b; s[l] = a; }
                }
            }
            __syncthreads();
        }
    }
    for (int i = tid; i < NN; i += blockDim.x) g_packed[i] = s[i];
}

__global__ void deg_kernel() {
    int t = blockIdx.x * blockDim.x + threadIdx.x;
    if (t >= NN) return;
    unsigned int p = g_packed[t];
    if (t == 0 || p != g_packed[t - 1]) {
        atomicAdd(&g_deg[p >> 13], 1);   // integer atomic: deterministic
    }
}

__global__ void dinv_kernel() {
    int i = blockIdx.x * blockDim.x + threadIdx.x;
    if (i >= NN) return;
    int d = g_deg[i];
    g_dinvf[i] = (d > 0) ? (float)(1.0 / sqrt((double)d)) : 0.0f;
}

// one warp per sorted edge slot: contribution dinv_i*sim*dinv_j into g_edot[t]
// duplicates get 0 so the row sum counts each unique edge once.
__global__ void dots_kernel(const float* __restrict__ x) {
    int t = (blockIdx.x * blockDim.x + threadIdx.x) >> 5;
    int lane = threadIdx.x & 31;
    if (t >= NN) return;
    unsigned int p = g_packed[t];
    if (t > 0 && p == g_packed[t - 1]) return;  // duplicate edge: g_edot stays 0
    int i = (int)(p >> 13), j = (int)(p & 8191u);
    float ni = fmaxf(g_norm[i], 1e-12f);
    float nj = fmaxf(g_norm[j], 1e-12f);
    const float4* ri = (const float4*)(x + (size_t)i * DD);
    const float4* rj = (const float4*)(x + (size_t)j * DD);
    float4 a = ri[lane], b = rj[lane];
    // elementwise f32 normalize (matches reference quantization), dot in double
    float ax = a.x / ni, ay = a.y / ni, az = a.z / ni, aw = a.w / ni;
    float bx = b.x / nj, by = b.y / nj, bz = b.z / nj, bw = b.w / nj;
    double s = (double)ax * bx + (double)ay * by + (double)az * bz + (double)aw * bw;
    #pragma unroll
    for (int o = 16; o > 0; o >>= 1) s += __shfl_down_sync(0xffffffffu, s, o);
    if (lane == 0) {
        g_edot[t] = (double)g_dinvf[i] * (double)g_dinvf[j] * s;
    }
}

// deterministic per-row segment sum over the sorted edge slots
__global__ void rowsum_kernel() {
    int t = blockIdx.x * blockDim.x + threadIdx.x;
    if (t >= NN) return;
    unsigned int row = g_packed[t] >> 13;
    if (t > 0 && (g_packed[t - 1] >> 13) == row) return;  // not a segment head
    double s = 0.0;
    #pragma unroll 1
    for (int u = t; u < NN && (g_packed[u] >> 13) == row; u++) s += g_edot[u];
    g_wf[row] = (float)s;
}

// build top-k keys: descending weight, ascending index on ties (jax top_k order)
__global__ void keys_kernel() {
    int i = blockIdx.x * blockDim.x + threadIdx.x;
    if (i >= NN) return;
    unsigned int u = __float_as_uint(g_wf[i]);
    unsigned int m = (u & 0x80000000u) ? ~u : (u | 0x80000000u);  // ascending monotone
    unsigned long long key = ((unsigned long long)(~m) << 32) | (unsigned int)i;
    g_keys[i] = key;
}

// bitonic sort of 8192 uint64 in one block (64KB dynamic smem)
__global__ void sort64_kernel() {
    extern __shared__ unsigned long long s64[];
    int tid = threadIdx.x;
    for (int i = tid; i < NN; i += blockDim.x) s64[i] = g_keys[i];
    __syncthreads();
    for (int k = 2; k <= NN; k <<= 1) {
        for (int j = k >> 1; j > 0; j >>= 1) {
            for (int i = tid; i < NN; i += blockDim.x) {
                int l = i ^ j;
                if (l > i) {
                    unsigned long long a = s64[i], b = s64[l];
                    bool asc = ((i & k) == 0);
                    if ((a > b) == asc) { s64[i] = b; s64[l] = a; }
                }
            }
            __syncthreads();
        }
    }
    for (int i = tid; i < NN; i += blockDim.x) g_keys[i] = s64[i];
}

__global__ void postsort_kernel() {
    int k = blockIdx.x * blockDim.x + threadIdx.x;
    if (k >= KK) return;
    int idx = (int)(g_keys[k] & 0xFFFFFFFFull);
    g_perm[k] = idx;
    g_sel[idx] = 1;
    g_newmask[idx] = k;
}

// single-block scan over !sel -> keep positions; emit remapped edge rows
__global__ void scan_emit_kernel(float* __restrict__ out) {
    __shared__ int sm[1024];
    int tid = threadIdx.x;
    int i0 = tid * 8;
    int loc[8];
    int c = 0;
    #pragma unroll
    for (int q = 0; q < 8; q++) {
        loc[q] = c;
        c += (g_sel[i0 + q] == 0) ? 1 : 0;
    }
    sm[tid] = c;
    __syncthreads();
    // Hillis-Steele inclusive scan over 1024
    for (int off = 1; off < 1024; off <<= 1) {
        int v = (tid >= off) ? sm[tid - off] : 0;
        __syncthreads();
        sm[tid] += v;
        __syncthreads();
    }
    int base = sm[tid] - c;  // exclusive
    const int OFF_E = KK * DD;
    #pragma unroll
    for (int q = 0; q < 8; q++) {
        int i = i0 + q;
        if (g_sel[i] == 0) {
            int pos = base + loc[q];
            out[OFF_E + pos]         = (float)g_newmask[g_ei[i]];
            out[OFF_E + NKEEP + pos] = (float)g_newmask[g_ej[i]];
        }
    }
}

// gather x_pool + tail outputs (perm, batch_pool, weights[perm])
__global__ void gather_kernel(const float* __restrict__ x,
                              const void* __restrict__ batch,
                              float* __restrict__ out) {
    int gid = blockIdx.x * blockDim.x + threadIdx.x;
    if (gid >= KK * DD) return;
    int k = gid >> 7;          // / 128
    int d = gid & 127;
    int p = g_perm[k];
    out[gid] = x[(size_t)p * DD + d];
    if (gid < KK) {
        const int OFF_PERM  = KK * DD + 2 * NKEEP;
        const int OFF_BATCH = OFF_PERM + KK;
        const int OFF_W     = OFF_BATCH + KK;
        int pp = g_perm[gid];
        long long bv;
        if (g_is64) bv = ((const long long*)batch)[pp];
        else        bv = (long long)((const int*)batch)[pp];
        out[OFF_PERM + gid]  = (float)pp;
        out[OFF_BATCH + gid] = (float)bv;
        out[OFF_W + gid]     = g_wf[pp];
    }
}

// ---------------- launch ----------------
extern "C" void kernel_launch(void* const* d_in, const int* in_sizes, int n_in,
                              void* d_out, int out_size) {
    const float* x     = (const float*)d_in[0];
    const void*  edges = d_in[1];
    const void*  batch = d_in[2];
    float* out = (float*)d_out;

    cudaFuncSetAttribute(sort64_kernel, cudaFuncAttributeMaxDynamicSharedMemorySize, 65536);

    zero_kernel<<<32, 256>>>();
    detect_kernel<<<1, 1>>>((const unsigned int*)edges);
    norms_kernel<<<NN / 8, 256>>>(x);        // 8 warps/block
    pack_kernel<<<32, 256>>>(edges);
    sort32_kernel<<<1, 1024>>>();
    deg_kernel<<<32, 256>>>();
    dinv_kernel<<<32, 256>>>();
    dots_kernel<<<NN / 8, 256>>>(x);         // warp per sorted edge slot
    rowsum_kernel<<<32, 256>>>();
    keys_kernel<<<32, 256>>>();
    sort64_kernel<<<1, 1024, 65536>>>();
    postsort_kernel<<<16, 256>>>();
    scan_emit_kernel<<<1, 1024>>>(out);
    gather_kernel<<<(KK * DD) / 256, 256>>>(x, batch, out);
}

// round 3
// speedup vs baseline: 1.4736x; 1.4736x over previous
#include <cuda_runtime.h>
#include <cuda_bf16.h>
#include <stdint.h>

#define NN 8192
#define DD 128
#define KK 4096         // K = N/2
#define NKEEP (NN - KK) // 4096
#define WPR 256         // 32-bit words per adjacency row (8192/32)

typedef unsigned long long u64;
typedef unsigned int u32;

// ---------------- device scratch (statics are zero-init at module load) ---
__device__ u32    g_adj[NN * WPR];   // adjacency bitmap, 8MB; invariant: zero on entry
__device__ float  g_norm[NN];
__device__ float  g_dinvf[NN];
__device__ float  g_wf[NN];
__device__ u64    g_keys[NN];
__device__ int    g_ei[NN];
__device__ int    g_ej[NN];
__device__ int    g_perm[KK];
__device__ int    g_is64;

// ============ K1: norms (warp/row) + edge decode + bitmap set =============
__global__ void k1_norms_pack(const float* __restrict__ x,
                              const void* __restrict__ edges) {
    int tid  = threadIdx.x;
    int wid  = tid >> 5;
    int lane = tid & 31;
    int row  = blockIdx.x * 8 + wid;

    // norms: warp per row, double sumsq
    const float4* rp = (const float4*)(x + (size_t)row * DD);
    float4 v = rp[lane];
    double s = (double)v.x * v.x + (double)v.y * v.y + (double)v.z * v.z + (double)v.w * v.w;
    #pragma unroll
    for (int o = 16; o > 0; o >>= 1) s += __shfl_down_sync(0xffffffffu, s, o);
    if (lane == 0) g_norm[row] = (float)sqrt(s);

    // blocks 0..31 also decode 256 edges each + set bits
    if (blockIdx.x < 32) {
        // per-warp dtype detect: odd 32-bit words of first 64 entries all zero <=> int64
        const u32* e32 = (const u32*)edges;
        u32 odd = e32[2 * lane + 1] | e32[2 * (lane + 32) + 1];
        int is64 = !__any_sync(0xffffffffu, odd != 0u);
        if (blockIdx.x == 0 && tid == 0) g_is64 = is64;

        int e = blockIdx.x * 256 + tid;
        int i, j;
        if (is64) {
            const long long* p = (const long long*)edges;
            i = (int)p[e];
            j = (int)p[NN + e];
        } else {
            const int* p = (const int*)edges;
            i = p[e];
            j = p[NN + e];
        }
        g_ei[e] = i;
        g_ej[e] = j;
        atomicOr(&g_adj[i * WPR + (j >> 5)], 1u << (j & 31));
    }
}

// ============ K2: deg via popcount, dinv ==================================
__global__ void k2_dinv() {
    int tid  = threadIdx.x;
    int lane = tid & 31;
    int node = blockIdx.x * 8 + (tid >> 5);
    const u32* row = &g_adj[node * WPR];
    int c = 0;
    #pragma unroll
    for (int t = 0; t < 8; t++) c += __popc(row[t * 32 + lane]);
    #pragma unroll
    for (int o = 16; o > 0; o >>= 1) c += __shfl_down_sync(0xffffffffu, c, o);
    if (lane == 0)
        g_dinvf[node] = (c > 0) ? (float)(1.0 / sqrt((double)c)) : 0.0f;
}

// ============ K3: per-node weights (deterministic) + topk keys ============
__global__ void k3_weights(const float* __restrict__ x) {
    int tid  = threadIdx.x;
    int lane = tid & 31;
    int node = blockIdx.x * 8 + (tid >> 5);

    float ni = fmaxf(g_norm[node], 1e-12f);
    float4 a = ((const float4*)(x + (size_t)node * DD))[lane];
    float ax = a.x / ni, ay = a.y / ni, az = a.z / ni, aw = a.w / ni;

    const u32* row = &g_adj[node * WPR];
    double acc = 0.0;
    for (int w = 0; w < WPR; w++) {
        u32 bits = row[w];               // broadcast load, uniform across warp
        while (bits) {
            int b = __ffs(bits) - 1;
            bits &= bits - 1;
            int j = w * 32 + b;
            float nj = fmaxf(g_norm[j], 1e-12f);
            float4 bv = ((const float4*)(x + (size_t)j * DD))[lane];
            float bx = bv.x / nj, by = bv.y / nj, bz = bv.z / nj, bw = bv.w / nj;
            double s = (double)ax * bx + (double)ay * by + (double)az * bz + (double)aw * bw;
            #pragma unroll
            for (int o = 16; o > 0; o >>= 1) s += __shfl_down_sync(0xffffffffu, s, o);
            if (lane == 0) acc += s * (double)g_dinvf[j];
        }
    }
    if (lane == 0) {
        float wf = (float)((double)g_dinvf[node] * acc);
        g_wf[node] = wf;
        u32 u = __float_as_uint(wf);
        u32 m = (u & 0x80000000u) ? ~u : (u | 0x80000000u);  // ascending monotone
        g_keys[node] = ((u64)(~m) << 32) | (u32)node;        // asc sort -> topk first, ties by idx
    }
}

// ============ K4: single-block sort + postsort + scan + edge emit =========
// dynamic smem: keys 64KB | nmask(u16) 16KB | sel(u8) 8KB | scan(int) 4KB
#define SM_KEYS_B   0
#define SM_NMASK_B  65536
#define SM_SEL_B    (65536 + 16384)
#define SM_SCAN_B   (65536 + 16384 + 8192)
#define SM_TOTAL_B  (65536 + 16384 + 8192 + 4096)

__global__ void k4_sort_emit(float* __restrict__ out) {
    extern __shared__ char sm[];
    u64* keys  = (u64*)(sm + SM_KEYS_B);
    unsigned short* nmask = (unsigned short*)(sm + SM_NMASK_B);
    unsigned char*  sel   = (unsigned char*)(sm + SM_SEL_B);
    int* scn   = (int*)(sm + SM_SCAN_B);
    int tid = threadIdx.x;

    #pragma unroll
    for (int q = 0; q < 8; q++) keys[tid + q * 1024] = g_keys[tid + q * 1024];
    __syncthreads();

    // ---- bitonic sort, ascending ----
    for (int k = 2; k <= NN; k <<= 1) {
        // cross-thread phases (j >= 8): pair-indexed
        for (int j = k >> 1; j >= 8; j >>= 1) {
            #pragma unroll
            for (int q = 0; q < 4; q++) {
                int p = tid + q * 1024;                     // 4096 pairs
                int i = ((p & ~(j - 1)) << 1) | (p & (j - 1));
                int l = i | j;
                u64 A = keys[i], B = keys[l];
                bool asc = ((i & k) == 0);
                if ((A > B) == asc) { keys[i] = B; keys[l] = A; }
            }
            __syncthreads();
        }
        // intra-thread phases (j <= 4): registers, one smem round
        {
            int base = tid * 8;
            u64 r[8];
            #pragma unroll
            for (int q = 0; q < 8; q++) r[q] = keys[base + q];
            #pragma unroll
            for (int j = 4; j >= 1; j >>= 1) {
                if (j <= (k >> 1)) {
                    #pragma unroll
                    for (int q = 0; q < 8; q++) {
                        if ((q & j) == 0) {
                            bool asc = (((base + q) & k) == 0);
                            u64 A = r[q], B = r[q | j];
                            if ((A > B) == asc) { r[q] = B; r[q | j] = A; }
                        }
                    }
                }
            }
            #pragma unroll
            for (int q = 0; q < 8; q++) keys[base + q] = r[q];
            __syncthreads();
        }
    }

    // ---- zero sel/nmask ----
    #pragma unroll
    for (int q = 0; q < 8; q++) { sel[tid + q * 1024] = 0; nmask[tid + q * 1024] = 0; }
    __syncthreads();

    // ---- postsort: perm, sel, newmask ----
    #pragma unroll
    for (int q = 0; q < 4; q++) {
        int k = tid + q * 1024;                 // k < KK
        int idx = (int)(keys[k] & 0xFFFFFFFFull);
        g_perm[k] = idx;
        sel[idx] = 1;
        nmask[idx] = (unsigned short)k;
    }
    __syncthreads();

    // ---- scan over !sel (edge-slot filter) + emit remapped edges ----
    int i0 = tid * 8;
    int loc[8];
    int c = 0;
    #pragma unroll
    for (int q = 0; q < 8; q++) { loc[q] = c; c += (sel[i0 + q] == 0) ? 1 : 0; }
    scn[tid] = c;
    __syncthreads();
    for (int off = 1; off < 1024; off <<= 1) {
        int v = (tid >= off) ? scn[tid - off] : 0;
        __syncthreads();
        scn[tid] += v;
        __syncthreads();
    }
    int base = scn[tid] - c;  // exclusive
    const int OFF_E = KK * DD;
    #pragma unroll
    for (int q = 0; q < 8; q++) {
        int i = i0 + q;
        if (sel[i] == 0) {
            int pos = base + loc[q];
            out[OFF_E + pos]         = (float)nmask[g_ei[i]];
            out[OFF_E + NKEEP + pos] = (float)nmask[g_ej[i]];
        }
    }
}

// ============ K5: gather x_pool + tail outputs + bitmap cleanup ===========
__global__ void k5_gather(const float* __restrict__ x,
                          const void* __restrict__ batch,
                          float* __restrict__ out) {
    int gid = blockIdx.x * blockDim.x + threadIdx.x;
    int k = gid >> 7;          // / 128
    int d = gid & 127;
    int p = g_perm[k];
    out[gid] = x[(size_t)p * DD + d];

    if (gid < KK) {
        const int OFF_PERM  = KK * DD + 2 * NKEEP;
        const int OFF_BATCH = OFF_PERM + KK;
        const int OFF_W     = OFF_BATCH + KK;
        int pp = g_perm[gid];
        long long bv;
        if (g_is64) bv = ((const long long*)batch)[pp];
        else        bv = (long long)((const int*)batch)[pp];
        out[OFF_PERM + gid]  = (float)pp;
        out[OFF_BATCH + gid] = (float)bv;
        out[OFF_W + gid]     = g_wf[pp];
    }
    // restore bitmap zero-invariant: clear every word touched by an edge
    if (gid < NN) {
        g_adj[g_ei[gid] * WPR + (g_ej[gid] >> 5)] = 0u;
    }
}

// ---------------- launch ----------------
extern "C" void kernel_launch(void* const* d_in, const int* in_sizes, int n_in,
                              void* d_out, int out_size) {
    const float* x     = (const float*)d_in[0];
    const void*  edges = d_in[1];
    const void*  batch = d_in[2];
    float* out = (float*)d_out;

    cudaFuncSetAttribute(k4_sort_emit, cudaFuncAttributeMaxDynamicSharedMemorySize, SM_TOTAL_B);

    k1_norms_pack<<<1024, 256>>>(x, edges);
    k2_dinv<<<1024, 256>>>();
    k3_weights<<<1024, 256>>>(x);
    k4_sort_emit<<<1, 1024, SM_TOTAL_B>>>(out);
    k5_gather<<<(KK * DD) / 256, 256>>>(x, batch, out);
}

// round 4
// speedup vs baseline: 4.5137x; 3.0631x over previous
#include <cuda_runtime.h>
#include <cuda_bf16.h>
#include <stdint.h>

#define NN 8192
#define DD 128
#define KK 4096         // K = N/2
#define NKEEP (NN - KK) // 4096
#define WPR 256         // 32-bit words per adjacency row

typedef unsigned long long u64;
typedef unsigned int u32;

// ---------------- device scratch (zero-init at load; invariants restored by k5)
__device__ u32   g_adj[NN * WPR];   // adjacency bitmap, 8MB; zero on entry
__device__ int   g_deg[NN];         // zero on entry
__device__ int   g_rank[NN];        // zero on entry
__device__ float g_norm[NN];
__device__ float g_wf[NN];
__device__ u32   g_mw[NN];          // ascending key: smaller = higher weight
__device__ int   g_ei[NN];
__device__ int   g_ej[NN];
__device__ int   g_perm[KK];
__device__ int   g_is64;

// ============ K1: norms (warp/row) + edge decode + bitmap + deg ===========
__global__ void k1_norms_pack(const float* __restrict__ x,
                              const void* __restrict__ edges) {
    int tid  = threadIdx.x;
    int wid  = tid >> 5;
    int lane = tid & 31;
    int row  = blockIdx.x * 8 + wid;

    // norms: warp per row, double sumsq
    const float4* rp = (const float4*)(x + (size_t)row * DD);
    float4 v = rp[lane];
    double s = (double)v.x * v.x + (double)v.y * v.y + (double)v.z * v.z + (double)v.w * v.w;
    #pragma unroll
    for (int o = 16; o > 0; o >>= 1) s += __shfl_down_sync(0xffffffffu, s, o);
    if (lane == 0) g_norm[row] = (float)sqrt(s);

    // blocks 0..31 also decode 256 edges each + set bits + count unique deg
    if (blockIdx.x < 32) {
        // per-warp dtype detect: odd 32-bit words of first 64 entries all zero <=> int64
        const u32* e32 = (const u32*)edges;
        u32 odd = e32[2 * lane + 1] | e32[2 * (lane + 32) + 1];
        int is64 = !__any_sync(0xffffffffu, odd != 0u);
        if (blockIdx.x == 0 && tid == 0) g_is64 = is64;

        int e = blockIdx.x * 256 + tid;
        int i, j;
        if (is64) {
            const long long* p = (const long long*)edges;
            i = (int)p[e];
            j = (int)p[NN + e];
        } else {
            const int* p = (const int*)edges;
            i = p[e];
            j = p[NN + e];
        }
        g_ei[e] = i;
        g_ej[e] = j;
        u32 bit = 1u << (j & 31);
        u32 old = atomicOr(&g_adj[i * WPR + (j >> 5)], bit);
        if (!(old & bit)) atomicAdd(&g_deg[i], 1);   // unique edge: deterministic
    }
}

// ============ K3: per-node weights (deterministic order) + keys ===========
__global__ void k3_weights(const float* __restrict__ x) {
    int tid  = threadIdx.x;
    int lane = tid & 31;
    int node = blockIdx.x * 8 + (tid >> 5);

    float ni = fmaxf(g_norm[node], 1e-12f);
    float4 a = ((const float4*)(x + (size_t)node * DD))[lane];
    float ax = a.x / ni, ay = a.y / ni, az = a.z / ni, aw = a.w / ni;

    const u32* row = &g_adj[node * WPR];
    double acc = 0.0;
    #pragma unroll
    for (int t = 0; t < 8; t++) {
        u32 w = row[t * 32 + lane];                      // per-lane word
        u32 wm = __ballot_sync(0xffffffffu, w != 0u);
        while (wm) {                                     // ascending src => ascending j
            int src = __ffs(wm) - 1;
            wm &= wm - 1;
            u32 bits = __shfl_sync(0xffffffffu, w, src);
            int jbase = (t * 32 + src) * 32;
            while (bits) {
                int b = __ffs(bits) - 1;
                bits &= bits - 1;
                int j = jbase + b;
                float nj = fmaxf(g_norm[j], 1e-12f);
                float4 bv = ((const float4*)(x + (size_t)j * DD))[lane];
                float bx = bv.x / nj, by = bv.y / nj, bz = bv.z / nj, bw = bv.w / nj;
                double s = (double)ax * bx + (double)ay * by + (double)az * bz + (double)aw * bw;
                #pragma unroll
                for (int o = 16; o > 0; o >>= 1) s += __shfl_down_sync(0xffffffffu, s, o);
                if (lane == 0) {
                    int dj = g_deg[j];
                    float dinvj = (dj > 0) ? (float)(1.0 / sqrt((double)dj)) : 0.0f;
                    acc += s * (double)dinvj;            // identical numerics to R3
                }
            }
        }
    }
    if (lane == 0) {
        int dn = g_deg[node];
        float dinvn = (dn > 0) ? (float)(1.0 / sqrt((double)dn)) : 0.0f;
        float wf = (float)((double)dinvn * acc);
        g_wf[node] = wf;
        u32 u = __float_as_uint(wf);
        u32 m = (u & 0x80000000u) ? ~u : (u | 0x80000000u);  // ascending monotone
        g_mw[node] = ~m;   // smaller = larger weight -> ascending rank = topk order
    }
}

// ============ K4a: direct rank computation (replaces the sort) ============
// blockIdx: low 5 bits = node chunk (256 nodes), high 3 bits = j chunk (1024 keys)
__global__ void k4a_rank() {
    __shared__ u64 sk[1024];
    int tid = threadIdx.x;                   // 256 threads
    int bn = blockIdx.x & 31;
    int bj = blockIdx.x >> 5;
    int jbase = bj * 1024;
    #pragma unroll
    for (int q = 0; q < 4; q++) {
        int i = tid + q * 256;
        int j = jbase + i;
        sk[i] = ((u64)g_mw[j] << 13) | (u32)j;
    }
    __syncthreads();

    int node = bn * 256 + tid;
    u64 my = ((u64)g_mw[node] << 13) | (u32)node;
    int cnt = 0;
    const ulonglong2* sk2 = (const ulonglong2*)sk;
    #pragma unroll 8
    for (int i = 0; i < 512; i++) {          // broadcast LDS.128: 2 keys/load
        ulonglong2 p = sk2[i];
        cnt += (p.x < my) + (p.y < my);
    }
    atomicAdd(&g_rank[node], cnt);           // integer: deterministic
}

// ============ K4b: single block: perm/sel/nmask + scan + edge emit ========
__global__ void k4b_emit(float* __restrict__ out) {
    __shared__ unsigned short nmask[NN];     // 16KB
    __shared__ unsigned char  selm[NN];      // 8KB
    __shared__ int scn[1024];
    int tid = threadIdx.x;

    #pragma unroll
    for (int q = 0; q < 8; q++) nmask[tid + q * 1024] = 0;
    __syncthreads();

    #pragma unroll
    for (int q = 0; q < 8; q++) {
        int node = tid + q * 1024;
        int r = g_rank[node];
        unsigned char s = (r < KK) ? 1 : 0;
        selm[node] = s;
        if (s) {
            g_perm[r] = node;                // unique ranks: race-free
            nmask[node] = (unsigned short)r; // new id = rank
        }
    }
    __syncthreads();

    // scan over !sel in node order; kept edge slots = unselected node ids
    int i0 = tid * 8;
    int loc[8];
    int c = 0;
    #pragma unroll
    for (int q = 0; q < 8; q++) { loc[q] = c; c += (selm[i0 + q] == 0) ? 1 : 0; }
    scn[tid] = c;
    __syncthreads();
    for (int off = 1; off < 1024; off <<= 1) {
        int v = (tid >= off) ? scn[tid - off] : 0;
        __syncthreads();
        scn[tid] += v;
        __syncthreads();
    }
    int base = scn[tid] - c;  // exclusive
    const int OFF_E = KK * DD;
    #pragma unroll
    for (int q = 0; q < 8; q++) {
        int i = i0 + q;
        if (selm[i] == 0) {
            int pos = base + loc[q];
            out[OFF_E + pos]         = (float)nmask[g_ei[i]];
            out[OFF_E + NKEEP + pos] = (float)nmask[g_ej[i]];
        }
    }
}

// ============ K5: gather x_pool + tail outputs + invariant restore ========
__global__ void k5_gather(const float* __restrict__ x,
                          const void* __restrict__ batch,
                          float* __restrict__ out) {
    int gid = blockIdx.x * blockDim.x + threadIdx.x;
    int k = gid >> 7;          // / 128
    int d = gid & 127;
    int p = g_perm[k];
    out[gid] = x[(size_t)p * DD + d];

    if (gid < KK) {
        const int OFF_PERM  = KK * DD + 2 * NKEEP;
        const int OFF_BATCH = OFF_PERM + KK;
        const int OFF_W     = OFF_BATCH + KK;
        int pp = g_perm[gid];
        long long bv;
        if (g_is64) bv = ((const long long*)batch)[pp];
        else        bv = (long long)((const int*)batch)[pp];
        out[OFF_PERM + gid]  = (float)pp;
        out[OFF_BATCH + gid] = (float)bv;
        out[OFF_W + gid]     = g_wf[pp];
    }
    // restore zero-invariants for next graph replay
    if (gid < NN) {
        g_adj[g_ei[gid] * WPR + (g_ej[gid] >> 5)] = 0u;
        g_deg[gid]  = 0;
        g_rank[gid] = 0;
    }
}

// ---------------- launch ----------------
extern "C" void kernel_launch(void* const* d_in, const int* in_sizes, int n_in,
                              void* d_out, int out_size) {
    const float* x     = (const float*)d_in[0];
    const void*  edges = d_in[1];
    const void*  batch = d_in[2];
    float* out = (float*)d_out;

    k1_norms_pack<<<1024, 256>>>(x, edges);
    k3_weights<<<1024, 256>>>(x);
    k4a_rank<<<256, 256>>>();
    k4b_emit<<<1, 1024>>>(out);
    k5_gather<<<(KK * DD) / 256, 256>>>(x, batch, out);
}

// round 5
// speedup vs baseline: 5.2778x; 1.1693x over previous
#include <cuda_runtime.h>
#include <cuda_bf16.h>
#include <stdint.h>

#define NN 8192
#define DD 128
#define KK 4096         // K = N/2
#define NKEEP (NN - KK) // 4096
#define WPR 256         // 32-bit words per adjacency row

typedef unsigned long long u64;
typedef unsigned int u32;

// ---------------- device scratch (zero-init at load; invariants restored by k5)
__device__ u32   g_adj[NN * WPR];   // adjacency bitmap, 8MB; zero on entry
__device__ int   g_deg[NN];         // zero on entry
__device__ int   g_rank[NN];        // zero on entry
__device__ float g_norm[NN];
__device__ float g_wf[NN];
__device__ u32   g_mw[NN];          // ascending key: smaller = higher weight
__device__ int   g_ei[NN];
__device__ int   g_ej[NN];
__device__ int   g_perm[KK];
__device__ int   g_is64;

// ============ K1: norms (warp/row) + edge decode + bitmap + deg ===========
__global__ void k1_norms_pack(const float* __restrict__ x,
                              const void* __restrict__ edges) {
    int tid  = threadIdx.x;
    int wid  = tid >> 5;
    int lane = tid & 31;
    int row  = blockIdx.x * 8 + wid;

    // norms: warp per row, double sumsq
    const float4* rp = (const float4*)(x + (size_t)row * DD);
    float4 v = rp[lane];
    double s = (double)v.x * v.x + (double)v.y * v.y + (double)v.z * v.z + (double)v.w * v.w;
    #pragma unroll
    for (int o = 16; o > 0; o >>= 1) s += __shfl_down_sync(0xffffffffu, s, o);
    if (lane == 0) g_norm[row] = (float)sqrt(s);

    // blocks 0..31 also decode 256 edges each + set bits + count unique deg
    if (blockIdx.x < 32) {
        // per-warp dtype detect: odd 32-bit words of first 64 entries all zero <=> int64
        const u32* e32 = (const u32*)edges;
        u32 odd = e32[2 * lane + 1] | e32[2 * (lane + 32) + 1];
        int is64 = !__any_sync(0xffffffffu, odd != 0u);
        if (blockIdx.x == 0 && tid == 0) g_is64 = is64;

        int e = blockIdx.x * 256 + tid;
        int i, j;
        if (is64) {
            const long long* p = (const long long*)edges;
            i = (int)p[e];
            j = (int)p[NN + e];
        } else {
            const int* p = (const int*)edges;
            i = p[e];
            j = p[NN + e];
        }
        g_ei[e] = i;
        g_ej[e] = j;
        u32 bit = 1u << (j & 31);
        u32 old = atomicOr(&g_adj[i * WPR + (j >> 5)], bit);
        if (!(old & bit)) atomicAdd(&g_deg[i], 1);   // unique edge: deterministic
    }
}

// ============ K3: per-node weights (deterministic order) + keys ===========
__global__ void k3_weights(const float* __restrict__ x) {
    int tid  = threadIdx.x;
    int lane = tid & 31;
    int node = blockIdx.x * 8 + (tid >> 5);

    float ni = fmaxf(g_norm[node], 1e-12f);
    float4 a = ((const float4*)(x + (size_t)node * DD))[lane];
    float ax = a.x / ni, ay = a.y / ni, az = a.z / ni, aw = a.w / ni;

    const u32* row = &g_adj[node * WPR];
    double acc = 0.0;
    #pragma unroll
    for (int t = 0; t < 8; t++) {
        u32 w = row[t * 32 + lane];                      // per-lane word
        u32 wm = __ballot_sync(0xffffffffu, w != 0u);
        while (wm) {                                     // ascending src => ascending j
            int src = __ffs(wm) - 1;
            wm &= wm - 1;
            u32 bits = __shfl_sync(0xffffffffu, w, src);
            int jbase = (t * 32 + src) * 32;
            while (bits) {
                int b = __ffs(bits) - 1;
                bits &= bits - 1;
                int j = jbase + b;
                float nj = fmaxf(g_norm[j], 1e-12f);
                float4 bv = ((const float4*)(x + (size_t)j * DD))[lane];
                float bx = bv.x / nj, by = bv.y / nj, bz = bv.z / nj, bw = bv.w / nj;
                double s = (double)ax * bx + (double)ay * by + (double)az * bz + (double)aw * bw;
                #pragma unroll
                for (int o = 16; o > 0; o >>= 1) s += __shfl_down_sync(0xffffffffu, s, o);
                if (lane == 0) {
                    int dj = g_deg[j];
                    float dinvj = (dj > 0) ? (float)(1.0 / sqrt((double)dj)) : 0.0f;
                    acc += s * (double)dinvj;            // identical numerics to R3/R4
                }
            }
        }
    }
    if (lane == 0) {
        int dn = g_deg[node];
        float dinvn = (dn > 0) ? (float)(1.0 / sqrt((double)dn)) : 0.0f;
        float wf = (float)((double)dinvn * acc);
        g_wf[node] = wf;
        u32 u = __float_as_uint(wf);
        u32 m = (u & 0x80000000u) ? ~u : (u | 0x80000000u);  // ascending monotone
        g_mw[node] = ~m;   // smaller = larger weight -> ascending rank = topk order
    }
}

// ============ K4a: direct rank computation ================================
// blockIdx: low 5 bits = node chunk (256 nodes), high 3 bits = j chunk (1024 keys)
__global__ void k4a_rank() {
    __shared__ u64 sk[1024];
    int tid = threadIdx.x;                   // 256 threads
    int bn = blockIdx.x & 31;
    int bj = blockIdx.x >> 5;
    int jbase = bj * 1024;
    #pragma unroll
    for (int q = 0; q < 4; q++) {
        int i = tid + q * 256;
        int j = jbase + i;
        sk[i] = ((u64)g_mw[j] << 13) | (u32)j;
    }
    __syncthreads();

    int node = bn * 256 + tid;
    u64 my = ((u64)g_mw[node] << 13) | (u32)node;
    int cnt = 0;
    const ulonglong2* sk2 = (const ulonglong2*)sk;
    #pragma unroll 8
    for (int i = 0; i < 512; i++) {          // broadcast LDS.128: 2 keys/load
        ulonglong2 p = sk2[i];
        cnt += (p.x < my) + (p.y < my);
    }
    atomicAdd(&g_rank[node], cnt);           // integer: deterministic
}

// ============ K4b: parallel emit — pure function of g_rank ================
// 32 blocks x 256 threads. Each block builds the full "unselected" bitmap
// (256 words) from g_rank via coalesced ballots, prefix-popcounts it, then
// handles 256 edge slots: kept slot i goes to position = #unselected below i.
// new node id of e == rank[e] if selected else 0 (reference zeros-init mask).
__global__ void k4b_emit(float* __restrict__ out) {
    __shared__ u32 words[256];
    __shared__ int wpref[256];
    __shared__ int warpsum[8];
    int tid  = threadIdx.x;
    int lane = tid & 31;
    int wid  = tid >> 5;

    // build unselected bitmap: 32 coalesced rounds, one ballot word each
    #pragma unroll
    for (int q = 0; q < 32; q++) {
        int node = q * 256 + tid;
        int uns = (g_rank[node] >= KK) ? 1 : 0;
        u32 w = __ballot_sync(0xffffffffu, uns);
        if (lane == 0) words[q * 8 + wid] = w;
    }
    __syncthreads();

    // exclusive prefix of popcounts over 256 words (warp scans + combine)
    int c = __popc(words[tid]);
    int v = c;
    #pragma unroll
    for (int o = 1; o < 32; o <<= 1) {
        int t = __shfl_up_sync(0xffffffffu, v, o);
        if (lane >= o) v += t;
    }
    if (lane == 31) warpsum[wid] = v;
    __syncthreads();
    if (wid == 0) {
        int s = (lane < 8) ? warpsum[lane] : 0;
        #pragma unroll
        for (int o = 1; o < 8; o <<= 1) {
            int t = __shfl_up_sync(0xffffffffu, s, o);
            if (lane >= o) s += t;
        }
        if (lane < 8) warpsum[lane] = s;
    }
    __syncthreads();
    wpref[tid] = v - c + ((wid > 0) ? warpsum[wid - 1] : 0);
    __syncthreads();

    // this block's 256 slots: perm scatter + edge emit
    int i = blockIdx.x * 256 + tid;
    int r = g_rank[i];
    if (r < KK) {
        g_perm[r] = i;                        // unique ranks: race-free
    } else {
        int word = i >> 5;
        u32 w = words[word];
        int pos = wpref[word] + __popc(w & ((1u << (i & 31)) - 1u));
        int a = g_ei[i], b = g_ej[i];
        int ra = g_rank[a], rb = g_rank[b];
        const int OFF_E = KK * DD;
        out[OFF_E + pos]         = (float)((ra < KK) ? ra : 0);
        out[OFF_E + NKEEP + pos] = (float)((rb < KK) ? rb : 0);
    }
}

// ============ K5: gather x_pool + tail outputs + invariant restore ========
__global__ void k5_gather(const float* __restrict__ x,
                          const void* __restrict__ batch,
                          float* __restrict__ out) {
    int gid = blockIdx.x * blockDim.x + threadIdx.x;
    int k = gid >> 7;          // / 128
    int d = gid & 127;
    int p = g_perm[k];
    out[gid] = x[(size_t)p * DD + d];

    if (gid < KK) {
        const int OFF_PERM  = KK * DD + 2 * NKEEP;
        const int OFF_BATCH = OFF_PERM + KK;
        const int OFF_W     = OFF_BATCH + KK;
        int pp = g_perm[gid];
        long long bv;
        if (g_is64) bv = ((const long long*)batch)[pp];
        else        bv = (long long)((const int*)batch)[pp];
        out[OFF_PERM + gid]  = (float)pp;
        out[OFF_BATCH + gid] = (float)bv;
        out[OFF_W + gid]     = g_wf[pp];
    }
    // restore zero-invariants for next graph replay
    if (gid < NN) {
        g_adj[g_ei[gid] * WPR + (g_ej[gid] >> 5)] = 0u;
        g_deg[gid]  = 0;
        g_rank[gid] = 0;
    }
}

// ---------------- launch ----------------
extern "C" void kernel_launch(void* const* d_in, const int* in_sizes, int n_in,
                              void* d_out, int out_size) {
    const float* x     = (const float*)d_in[0];
    const void*  edges = d_in[1];
    const void*  batch = d_in[2];
    float* out = (float*)d_out;

    k1_norms_pack<<<1024, 256>>>(x, edges);
    k3_weights<<<1024, 256>>>(x);
    k4a_rank<<<256, 256>>>();
    k4b_emit<<<32, 256>>>(out);
    k5_gather<<<(KK * DD) / 256, 256>>>(x, batch, out);
}

// round 6
// speedup vs baseline: 5.5780x; 1.0569x over previous
#include <cuda_runtime.h>
#include <cuda_bf16.h>
#include <stdint.h>

#define NN 8192
#define DD 128
#define KK 4096         // K = N/2
#define NKEEP (NN - KK) // 4096
#define WPR 256         // 32-bit words per adjacency row

typedef unsigned long long u64;
typedef unsigned int u32;

// ---------------- device scratch ------------------------------------------
// zero-invariants: g_adj / g_deg restored by k45 tail blocks; g_rank zeroed
// by k3 (which runs before k4a's atomics) each call.
__device__ u32   g_adj[NN * WPR];   // adjacency bitmap, 8MB
__device__ int   g_deg[NN];
__device__ int   g_rank[NN];
__device__ float g_norm[NN];
__device__ float g_wf[NN];
__device__ u32   g_mw[NN];          // ascending key: smaller = higher weight
__device__ int   g_ei[NN];
__device__ int   g_ej[NN];
__device__ int   g_is64;

// ============ K1: norms (warp/row) + edge decode + bitmap + deg ===========
__global__ void k1_norms_pack(const float* __restrict__ x,
                              const void* __restrict__ edges) {
    int tid  = threadIdx.x;
    int wid  = tid >> 5;
    int lane = tid & 31;
    int row  = blockIdx.x * 8 + wid;

    // norms: warp per row, double sumsq
    const float4* rp = (const float4*)(x + (size_t)row * DD);
    float4 v = rp[lane];
    double s = (double)v.x * v.x + (double)v.y * v.y + (double)v.z * v.z + (double)v.w * v.w;
    #pragma unroll
    for (int o = 16; o > 0; o >>= 1) s += __shfl_down_sync(0xffffffffu, s, o);
    if (lane == 0) g_norm[row] = (float)sqrt(s);

    // blocks 0..31 also decode 256 edges each + set bits + count unique deg
    if (blockIdx.x < 32) {
        // per-warp dtype detect: odd 32-bit words of first 64 entries all zero <=> int64
        const u32* e32 = (const u32*)edges;
        u32 odd = e32[2 * lane + 1] | e32[2 * (lane + 32) + 1];
        int is64 = !__any_sync(0xffffffffu, odd != 0u);
        if (blockIdx.x == 0 && tid == 0) g_is64 = is64;

        int e = blockIdx.x * 256 + tid;
        int i, j;
        if (is64) {
            const long long* p = (const long long*)edges;
            i = (int)p[e];
            j = (int)p[NN + e];
        } else {
            const int* p = (const int*)edges;
            i = p[e];
            j = p[NN + e];
        }
        g_ei[e] = i;
        g_ej[e] = j;
        u32 bit = 1u << (j & 31);
        u32 old = atomicOr(&g_adj[i * WPR + (j >> 5)], bit);
        if (!(old & bit)) atomicAdd(&g_deg[i], 1);   // unique edge: deterministic
    }
}

// ============ K3: per-node weights (deterministic order) + keys + rank=0 ==
__global__ void k3_weights(const float* __restrict__ x) {
    int tid  = threadIdx.x;
    int lane = tid & 31;
    int node = blockIdx.x * 8 + (tid >> 5);

    float ni = fmaxf(g_norm[node], 1e-12f);
    float4 a = ((const float4*)(x + (size_t)node * DD))[lane];
    float ax = a.x / ni, ay = a.y / ni, az = a.z / ni, aw = a.w / ni;

    const u32* row = &g_adj[node * WPR];
    double acc = 0.0;
    #pragma unroll
    for (int t = 0; t < 8; t++) {
        u32 w = row[t * 32 + lane];                      // per-lane word
        u32 wm = __ballot_sync(0xffffffffu, w != 0u);
        while (wm) {                                     // ascending src => ascending j
            int src = __ffs(wm) - 1;
            wm &= wm - 1;
            u32 bits = __shfl_sync(0xffffffffu, w, src);
            int jbase = (t * 32 + src) * 32;
            while (bits) {
                int b = __ffs(bits) - 1;
                bits &= bits - 1;
                int j = jbase + b;
                float nj = fmaxf(g_norm[j], 1e-12f);
                float4 bv = ((const float4*)(x + (size_t)j * DD))[lane];
                float bx = bv.x / nj, by = bv.y / nj, bz = bv.z / nj, bw = bv.w / nj;
                double s = (double)ax * bx + (double)ay * by + (double)az * bz + (double)aw * bw;
                #pragma unroll
                for (int o = 16; o > 0; o >>= 1) s += __shfl_down_sync(0xffffffffu, s, o);
                if (lane == 0) {
                    int dj = g_deg[j];
                    float dinvj = (dj > 0) ? (float)(1.0 / sqrt((double)dj)) : 0.0f;
                    acc += s * (double)dinvj;            // identical numerics to R3-R5
                }
            }
        }
    }
    if (lane == 0) {
        int dn = g_deg[node];
        float dinvn = (dn > 0) ? (float)(1.0 / sqrt((double)dn)) : 0.0f;
        float wf = (float)((double)dinvn * acc);
        g_wf[node] = wf;
        u32 u = __float_as_uint(wf);
        u32 m = (u & 0x80000000u) ? ~u : (u | 0x80000000u);  // ascending monotone
        g_mw[node] = ~m;   // smaller = larger weight -> ascending rank = topk order
        g_rank[node] = 0;  // reset before k4a atomics (replay invariant)
    }
}

// ============ K4a: direct rank computation ================================
// blockIdx: low 5 bits = node chunk (256 nodes), high 3 bits = j chunk (1024 keys)
__global__ void k4a_rank() {
    __shared__ u64 sk[1024];
    int tid = threadIdx.x;                   // 256 threads
    int bn = blockIdx.x & 31;
    int bj = blockIdx.x >> 5;
    int jbase = bj * 1024;
    #pragma unroll
    for (int q = 0; q < 4; q++) {
        int i = tid + q * 256;
        int j = jbase + i;
        sk[i] = ((u64)g_mw[j] << 13) | (u32)j;
    }
    __syncthreads();

    int node = bn * 256 + tid;
    u64 my = ((u64)g_mw[node] << 13) | (u32)node;
    int cnt = 0;
    const ulonglong2* sk2 = (const ulonglong2*)sk;
    #pragma unroll 8
    for (int i = 0; i < 512; i++) {          // broadcast LDS.128: 2 keys/load
        ulonglong2 p = sk2[i];
        cnt += (p.x < my) + (p.y < my);
    }
    atomicAdd(&g_rank[node], cnt);           // integer: deterministic
}

// ============ K45: fused emit + gather + invariant restore ================
// grid 1024 x 256. All blocks: warp-per-node gather (node's output row == its
// rank, so no inverse permutation needed). Blocks 0..31: edge emit via
// unselected-bitmap prefix. Blocks 992..1023: clear adj/deg for next replay.
__global__ void k45_emit_gather(const float* __restrict__ x,
                                const void* __restrict__ batch,
                                float* __restrict__ out) {
    int tid  = threadIdx.x;
    int lane = tid & 31;
    int wid  = tid >> 5;

    // ---- gather: warp per node ----
    int node = blockIdx.x * 8 + wid;
    int r = g_rank[node];
    if (r < KK) {
        float4 v = ((const float4*)(x + (size_t)node * DD))[lane];
        ((float4*)(out + (size_t)r * DD))[lane] = v;
        if (lane == 0) {
            const int OFF_PERM  = KK * DD + 2 * NKEEP;
            const int OFF_BATCH = OFF_PERM + KK;
            const int OFF_W     = OFF_BATCH + KK;
            long long bv;
            if (g_is64) bv = ((const long long*)batch)[node];
            else        bv = (long long)((const int*)batch)[node];
            out[OFF_PERM + r]  = (float)node;
            out[OFF_BATCH + r] = (float)bv;
            out[OFF_W + r]     = g_wf[node];
        }
    }

    // ---- emit: blocks 0..31 ----
    if (blockIdx.x < 32) {
        __shared__ u32 words[256];
        __shared__ int wpref[256];
        __shared__ int warpsum[8];

        // unselected bitmap: 32 coalesced ballot rounds
        #pragma unroll
        for (int q = 0; q < 32; q++) {
            int n2 = q * 256 + tid;
            int uns = (g_rank[n2] >= KK) ? 1 : 0;
            u32 w = __ballot_sync(0xffffffffu, uns);
            if (lane == 0) words[q * 8 + wid] = w;
        }
        __syncthreads();

        // exclusive prefix of popcounts over 256 words
        int c = __popc(words[tid]);
        int v = c;
        #pragma unroll
        for (int o = 1; o < 32; o <<= 1) {
            int t = __shfl_up_sync(0xffffffffu, v, o);
            if (lane >= o) v += t;
        }
        if (lane == 31) warpsum[wid] = v;
        __syncthreads();
        if (wid == 0) {
            int s = (lane < 8) ? warpsum[lane] : 0;
            #pragma unroll
            for (int o = 1; o < 8; o <<= 1) {
                int t = __shfl_up_sync(0xffffffffu, s, o);
                if (lane >= o) s += t;
            }
            if (lane < 8) warpsum[lane] = s;
        }
        __syncthreads();
        wpref[tid] = v - c + ((wid > 0) ? warpsum[wid - 1] : 0);
        __syncthreads();

        // this block's 256 edge slots
        int i = blockIdx.x * 256 + tid;
        if (g_rank[i] >= KK) {               // kept slot
            int word = i >> 5;
            u32 w = words[word];
            int pos = wpref[word] + __popc(w & ((1u << (i & 31)) - 1u));
            int a = g_ei[i], b = g_ej[i];
            int ra = g_rank[a], rb = g_rank[b];
            const int OFF_E = KK * DD;
            out[OFF_E + pos]         = (float)((ra < KK) ? ra : 0);
            out[OFF_E + NKEEP + pos] = (float)((rb < KK) ? rb : 0);
        }
    }

    // ---- restore zero-invariants: blocks 992..1023 ----
    if (blockIdx.x >= 992) {
        int e = (blockIdx.x - 992) * 256 + tid;
        g_adj[g_ei[e] * WPR + (g_ej[e] >> 5)] = 0u;
        g_deg[e] = 0;
    }
}

// ---------------- launch ----------------
extern "C" void kernel_launch(void* const* d_in, const int* in_sizes, int n_in,
                              void* d_out, int out_size) {
    const float* x     = (const float*)d_in[0];
    const void*  edges = d_in[1];
    const void*  batch = d_in[2];
    float* out = (float*)d_out;

    k1_norms_pack<<<1024, 256>>>(x, edges);
    k3_weights<<<1024, 256>>>(x);
    k4a_rank<<<256, 256>>>();
    k45_emit_gather<<<1024, 256>>>(x, batch, out);
}